// round 4
// baseline (speedup 1.0000x reference)
#include <cuda_runtime.h>
#include <math.h>

#define NQB 4
#define BB  512
#define SS  256
#define DD  64
#define HH  128
#define FULL 0xffffffffu

__device__ __forceinline__ float2 cmul(float2 a, float2 b) {
    return make_float2(fmaf(a.x, b.x, -a.y * b.y), fmaf(a.x, b.y, a.y * b.x));
}
__device__ __forceinline__ float fsig(float x)  { return 1.0f / (1.0f + __expf(-x)); }
__device__ __forceinline__ float ftanh(float x) { return 2.0f / (1.0f + __expf(-2.0f * x)) - 1.0f; }

// source index after the CNOT ring (0,1)(1,2)(2,3)(3,0), gather form
__device__ __forceinline__ int cnot_src(int i) {
    i ^= (i & 1) ? 8 : 0;   // CNOT(3,0)
    i ^= (i & 2) ? 1 : 0;   // CNOT(2,3)
    i ^= (i & 4) ? 2 : 0;   // CNOT(1,2)
    i ^= (i & 8) ? 4 : 0;   // CNOT(0,1)
    return i;
}

__global__ __launch_bounds__(32)
void qlstm_kernel(const float* __restrict__ x,
                  const float* __restrict__ W_in,
                  const float* __restrict__ b_in,
                  const float* __restrict__ W_out,
                  const float* __restrict__ b_out,
                  const float* __restrict__ w_f,
                  const float* __restrict__ w_i,
                  const float* __restrict__ w_u,
                  const float* __restrict__ w_o,
                  float* __restrict__ out,
                  int write_tails)
{
    const int lane = threadIdx.x;
    const int b    = blockIdx.x;
    const int il   = lane & 15;              // amplitude index (shared by both slots)
    const int half = lane >> 4;              // 0: gates {0,2}, 1: gates {1,3}

    // ---- per-lane constant setup (registers only, no smem) ----
    // W_in rows for this lane's h dims (k = lane + 32r) and x dims (k = 128 + 2*lane + {0,1})
    float4 wiH[4];
    #pragma unroll
    for (int r = 0; r < 4; ++r)
        wiH[r] = *(const float4*)(W_in + 4 * (lane + 32 * r));
    float4 wiX0 = *(const float4*)(W_in + 4 * (HH + 2 * lane));
    float4 wiX1 = *(const float4*)(W_in + 4 * (HH + 2 * lane + 1));
    float4 binv = *(const float4*)(b_in);

    float wo[NQB][4], bo[4];
    #pragma unroll
    for (int j = 0; j < NQB; ++j)
        #pragma unroll
        for (int r = 0; r < 4; ++r)
            wo[j][r] = W_out[j * HH + lane + 32 * r];
    #pragma unroll
    for (int r = 0; r < 4; ++r) bo[r] = b_out[lane + 32 * r];

    // amp-bit per qubit for this lane
    bool hq[NQB];
    #pragma unroll
    for (int q = 0; q < NQB; ++q) hq[q] = (il >> (3 - q)) & 1;

    // fused ansatz matrices U = RZ*RY*RX (constant weights); keep only the row
    // this lane needs: v0 = U[hi][0], v1 = U[hi][1], per slot per qubit.
    float2 av0[2][NQB], av1[2][NQB];
    #pragma unroll
    for (int s = 0; s < 2; ++s) {
        const int  g  = 2 * s + half;
        const float* wg = (g == 0) ? w_f : (g == 1) ? w_i : (g == 2) ? w_u : w_o;
        #pragma unroll
        for (int q = 0; q < NQB; ++q) {
            float sa, ca, sb, cb, sg, cg;
            sincosf(wg[q]           * 0.5f, &sa, &ca);
            sincosf(wg[NQB + q]     * 0.5f, &sb, &cb);
            sincosf(wg[2 * NQB + q] * 0.5f, &sg, &cg);
            float2 m00 = make_float2( cb * ca,  sb * sa);
            float2 m01 = make_float2(-sb * ca, -cb * sa);
            float2 m10 = make_float2( sb * ca, -cb * sa);
            float2 m11 = make_float2( cb * ca, -sb * sa);
            float2 e0  = make_float2(cg, -sg);
            float2 e1  = make_float2(cg,  sg);
            if (hq[q]) { av0[s][q] = cmul(e1, m10); av1[s][q] = cmul(e1, m11); }
            else       { av0[s][q] = cmul(e0, m00); av1[s][q] = cmul(e0, m01); }
        }
    }

    // CNOT-ring-fused sources for the first ansatz gate (qubit 0, mask 8)
    const int src0 = cnot_src(il & 7);   // bit8 = 0 partner
    const int src1 = cnot_src(il | 8);   // bit8 = 1 partner

    const float* xb = x + (size_t)b * SS * DD;
    float2 xv = *(const float2*)(xb + 2 * lane);   // prefetched x_t slice

    float hreg[4] = {0.f, 0.f, 0.f, 0.f};
    float creg[4] = {0.f, 0.f, 0.f, 0.f};
    const float IS2 = 0.70710678118654752440f;

    for (int t = 0; t < SS; ++t) {
        // ---- 1. y = [h, x_t] @ W_in + b_in  (warp-internal reduce, no sync) ----
        float p0 = 0.f, p1 = 0.f, p2 = 0.f, p3 = 0.f;
        #pragma unroll
        for (int r = 0; r < 4; ++r) {
            p0 = fmaf(hreg[r], wiH[r].x, p0);
            p1 = fmaf(hreg[r], wiH[r].y, p1);
            p2 = fmaf(hreg[r], wiH[r].z, p2);
            p3 = fmaf(hreg[r], wiH[r].w, p3);
        }
        p0 = fmaf(xv.x, wiX0.x, fmaf(xv.y, wiX1.x, p0));
        p1 = fmaf(xv.x, wiX0.y, fmaf(xv.y, wiX1.y, p1));
        p2 = fmaf(xv.x, wiX0.z, fmaf(xv.y, wiX1.z, p2));
        p3 = fmaf(xv.x, wiX0.w, fmaf(xv.y, wiX1.w, p3));
        if (t + 1 < SS) xv = *(const float2*)(xb + (t + 1) * DD + 2 * lane);

        #pragma unroll
        for (int off = 16; off; off >>= 1) {
            p0 += __shfl_xor_sync(FULL, p0, off);
            p1 += __shfl_xor_sync(FULL, p1, off);
            p2 += __shfl_xor_sync(FULL, p2, off);
            p3 += __shfl_xor_sync(FULL, p3, off);
        }
        float yv[NQB] = { p0 + binv.x, p1 + binv.y, p2 + binv.z, p3 + binv.w };

        // ---- 2. encoding product state (trig-free, no shuffles) ----
        // w_q = bit ? B*(cz, sz) : (A, 0);  A=(ch-sh)/sqrt2, B=(ch+sh)/sqrt2
        // ch=cos(atan(y)/2), sh=sin(atan(y)/2); cz+isz = e^{i atan(y^2)} (global phase dropped)
        float2 amp;
        {
            float2 w[NQB];
            #pragma unroll
            for (int q = 0; q < NQB; ++q) {
                float y  = yv[q];
                float t2 = y * y;
                float r  = rsqrtf(1.f + t2);            // cos(atan y)
                float ch = sqrtf(0.5f * (1.f + r));
                float sh = __fdividef(0.5f * y * r, ch); // sin(theta/2), no cancellation
                float A  = (ch - sh) * IS2;
                float B  = (ch + sh) * IS2;
                float t4 = t2 * t2;
                float r2 = rsqrtf(1.f + t4);            // cos(atan y^2)
                w[q] = hq[q] ? make_float2(B * r2, B * (t2 * r2))
                             : make_float2(A, 0.f);
            }
            amp = cmul(cmul(w[0], w[1]), cmul(w[2], w[3]));
        }

        // ---- 3. ansatz: first gate fused with the CNOT ring permutation ----
        float2 a0, a1;
        a0.x = __shfl_sync(FULL, amp.x, src0, 16);
        a0.y = __shfl_sync(FULL, amp.y, src0, 16);
        a1.x = __shfl_sync(FULL, amp.x, src1, 16);
        a1.y = __shfl_sync(FULL, amp.y, src1, 16);

        float2 s0amp, s1amp;
        {
            float2 v0 = av0[0][0], v1 = av1[0][0];
            s0amp.x = v0.x*a0.x - v0.y*a0.y + v1.x*a1.x - v1.y*a1.y;
            s0amp.y = v0.x*a0.y + v0.y*a0.x + v1.x*a1.y + v1.y*a1.x;
            v0 = av0[1][0]; v1 = av1[1][0];
            s1amp.x = v0.x*a0.x - v0.y*a0.y + v1.x*a1.x - v1.y*a1.y;
            s1amp.y = v0.x*a0.y + v0.y*a0.x + v1.x*a1.y + v1.y*a1.x;
        }

        #pragma unroll
        for (int q = 1; q < NQB; ++q) {
            const int m = 8 >> q;
            const bool hi = hq[q];
            // slot 0
            {
                float ox = __shfl_xor_sync(FULL, s0amp.x, m, 16);
                float oy = __shfl_xor_sync(FULL, s0amp.y, m, 16);
                float a0x = hi ? ox : s0amp.x, a0y = hi ? oy : s0amp.y;
                float a1x = hi ? s0amp.x : ox, a1y = hi ? s0amp.y : oy;
                float2 v0 = av0[0][q], v1 = av1[0][q];
                s0amp.x = v0.x*a0x - v0.y*a0y + v1.x*a1x - v1.y*a1y;
                s0amp.y = v0.x*a0y + v0.y*a0x + v1.x*a1y + v1.y*a1x;
            }
            // slot 1
            {
                float ox = __shfl_xor_sync(FULL, s1amp.x, m, 16);
                float oy = __shfl_xor_sync(FULL, s1amp.y, m, 16);
                float a0x = hi ? ox : s1amp.x, a0y = hi ? oy : s1amp.y;
                float a1x = hi ? s1amp.x : ox, a1y = hi ? s1amp.y : oy;
                float2 v0 = av0[1][q], v1 = av1[1][q];
                s1amp.x = v0.x*a0x - v0.y*a0y + v1.x*a1x - v1.y*a1y;
                s1amp.y = v0.x*a0y + v0.y*a0x + v1.x*a1y + v1.y*a1x;
            }
        }

        // ---- 4. <Z_q> via 4-level Walsh-Hadamard butterfly per slot ----
        float w0 = s0amp.x * s0amp.x + s0amp.y * s0amp.y;
        float w1 = s1amp.x * s1amp.x + s1amp.y * s1amp.y;
        #pragma unroll
        for (int m = 8; m; m >>= 1) {
            float o0 = __shfl_xor_sync(FULL, w0, m, 16);
            float o1 = __shfl_xor_sync(FULL, w1, m, 16);
            w0 = (il & m) ? (o0 - w0) : (w0 + o0);
            w1 = (il & m) ? (o1 - w1) : (w1 + o1);
        }
        // lane (h*16 + maskq) of slot s holds z[gate 2s+h][q]; broadcast all 16
        float z[4][NQB];
        #pragma unroll
        for (int q = 0; q < NQB; ++q) {
            const int m = 8 >> q;
            z[0][q] = __shfl_sync(FULL, w0, m,      32);
            z[1][q] = __shfl_sync(FULL, w0, 16 + m, 32);
            z[2][q] = __shfl_sync(FULL, w1, m,      32);
            z[3][q] = __shfl_sync(FULL, w1, 16 + m, 32);
        }

        // ---- 5. projection + LSTM cell (4 hidden dims per lane) ----
        const size_t obase = ((size_t)b * SS + t) * HH + lane;
        #pragma unroll
        for (int r = 0; r < 4; ++r) {
            float af = bo[r], ai = bo[r], ag = bo[r], ao = bo[r];
            #pragma unroll
            for (int j = 0; j < NQB; ++j) {
                af = fmaf(z[0][j], wo[j][r], af);
                ai = fmaf(z[1][j], wo[j][r], ai);
                ag = fmaf(z[2][j], wo[j][r], ag);
                ao = fmaf(z[3][j], wo[j][r], ao);
            }
            float f = fsig(af), i = fsig(ai), g = ftanh(ag), o = fsig(ao);
            creg[r] = fmaf(f, creg[r], i * g);
            hreg[r] = o * ftanh(creg[r]);
            out[obase + 32 * r] = hreg[r];
        }
    }

    if (write_tails) {
        size_t base = (size_t)BB * SS * HH;
        #pragma unroll
        for (int r = 0; r < 4; ++r) {
            out[base + (size_t)b * HH + lane + 32 * r] = hreg[r];
            out[base + (size_t)BB * HH + (size_t)b * HH + lane + 32 * r] = creg[r];
        }
    }
}

extern "C" void kernel_launch(void* const* d_in, const int* in_sizes, int n_in,
                              void* d_out, int out_size) {
    const float* x     = (const float*)d_in[0];
    const float* W_in  = (const float*)d_in[1];
    const float* b_in  = (const float*)d_in[2];
    const float* W_out = (const float*)d_in[3];
    const float* b_out = (const float*)d_in[4];
    const float* w_f   = (const float*)d_in[5];
    const float* w_i   = (const float*)d_in[6];
    const float* w_u   = (const float*)d_in[7];
    const float* w_o   = (const float*)d_in[8];
    float* out = (float*)d_out;

    int need_tail = (size_t)out_size >= (size_t)BB * SS * HH + 2 * (size_t)BB * HH;
    qlstm_kernel<<<BB, 32>>>(x, W_in, b_in, W_out, b_out,
                             w_f, w_i, w_u, w_o, out, need_tail);
}

// round 5
// speedup vs baseline: 2.8673x; 2.8673x over previous
#include <cuda_runtime.h>
#include <math.h>

#define NQB 4
#define BB  512
#define SS  256
#define DD  64
#define HH  128
#define FULL 0xffffffffu

__device__ __forceinline__ float2 cmul(float2 a, float2 b) {
    return make_float2(fmaf(a.x, b.x, -a.y * b.y), fmaf(a.x, b.y, a.y * b.x));
}
__device__ __forceinline__ float fsig(float x)  { return 1.0f / (1.0f + __expf(-x)); }
__device__ __forceinline__ float ftanh(float x) { return 2.0f / (1.0f + __expf(-2.0f * x)) - 1.0f; }

// source index after the CNOT ring (0,1)(1,2)(2,3)(3,0), gather form
__device__ __forceinline__ int cnot_src(int i) {
    i ^= (i & 1) ? 8 : 0;   // CNOT(3,0)
    i ^= (i & 2) ? 1 : 0;   // CNOT(2,3)
    i ^= (i & 4) ? 2 : 0;   // CNOT(1,2)
    i ^= (i & 8) ? 4 : 0;   // CNOT(0,1)
    return i;
}

__global__ __launch_bounds__(128)
void qlstm_kernel(const float* __restrict__ x,
                  const float* __restrict__ W_in,
                  const float* __restrict__ b_in,
                  const float* __restrict__ W_out,
                  const float* __restrict__ b_out,
                  const float* __restrict__ w_f,
                  const float* __restrict__ w_i,
                  const float* __restrict__ w_u,
                  const float* __restrict__ w_o,
                  float* __restrict__ out,
                  int write_tails)
{
    __shared__ __align__(16) float sP[4][4];   // [j][warp] partial y sums
    __shared__ __align__(16) float sZ[4][4];   // [gate][qubit] <Z>

    const int tid  = threadIdx.x;
    const int lane = tid & 31;
    const int wid  = tid >> 5;          // warp = gate: 0=f 1=i 2=u 3=o
    const int il   = lane & 15;         // amplitude index (lanes 16-31 mirror)
    const int b    = blockIdx.x;

    // ---- per-thread constants (registers) ----
    float4 wi = *(const float4*)(W_in + 4 * tid);                 // W_in row for h-dim tid
    float4 wx = make_float4(0.f, 0.f, 0.f, 0.f);
    if (tid < DD) wx = *(const float4*)(W_in + 4 * (HH + tid));   // W_in row for x-dim tid
    float4 binv = *(const float4*)(b_in);
    float wo0 = W_out[tid], wo1 = W_out[HH + tid], wo2 = W_out[2*HH + tid], wo3 = W_out[3*HH + tid];
    float bo  = b_out[tid];

    bool  hq[NQB];
    float hs[NQB];
    #pragma unroll
    for (int q = 0; q < NQB; ++q) {
        hq[q] = (il >> (3 - q)) & 1;
        hs[q] = hq[q] ? 0.5f : -0.5f;
    }

    // fused ansatz U = RZ*RY*RX for THIS warp's gate; keep the row this lane needs
    float2 av0[NQB], av1[NQB];
    {
        const float* wg = (wid == 0) ? w_f : (wid == 1) ? w_i : (wid == 2) ? w_u : w_o;
        #pragma unroll
        for (int q = 0; q < NQB; ++q) {
            float sa, ca, sb, cb, sg, cg;
            sincosf(wg[q]           * 0.5f, &sa, &ca);
            sincosf(wg[NQB + q]     * 0.5f, &sb, &cb);
            sincosf(wg[2 * NQB + q] * 0.5f, &sg, &cg);
            float2 m00 = make_float2( cb * ca,  sb * sa);
            float2 m01 = make_float2(-sb * ca, -cb * sa);
            float2 m10 = make_float2( sb * ca, -cb * sa);
            float2 m11 = make_float2( cb * ca, -sb * sa);
            float2 e0  = make_float2(cg, -sg);
            float2 e1  = make_float2(cg,  sg);
            if (hq[q]) { av0[q] = cmul(e1, m10); av1[q] = cmul(e1, m11); }
            else       { av0[q] = cmul(e0, m00); av1[q] = cmul(e0, m01); }
        }
    }

    const int src0 = cnot_src(il & 7);   // bit8=0 partner, CNOT-ring fused
    const int src1 = cnot_src(il | 8);   // bit8=1 partner

    const float* xb = x + (size_t)b * SS * DD;
    float xv = (tid < DD) ? xb[tid] : 0.f;

    float h = 0.f, c = 0.f;

    for (int t = 0; t < SS; ++t) {
        // ---- 1. y = [h, x_t] @ W_in + b_in (warp reduce + smem combine) ----
        float p0 = fmaf(h, wi.x, xv * wx.x);
        float p1 = fmaf(h, wi.y, xv * wx.y);
        float p2 = fmaf(h, wi.z, xv * wx.z);
        float p3 = fmaf(h, wi.w, xv * wx.w);
        if (tid < DD && t + 1 < SS) xv = xb[(t + 1) * DD + tid];   // prefetch

        #pragma unroll
        for (int off = 16; off; off >>= 1) {
            p0 += __shfl_xor_sync(FULL, p0, off);
            p1 += __shfl_xor_sync(FULL, p1, off);
            p2 += __shfl_xor_sync(FULL, p2, off);
            p3 += __shfl_xor_sync(FULL, p3, off);
        }
        if (lane == 0) {
            sP[0][wid] = p0; sP[1][wid] = p1; sP[2][wid] = p2; sP[3][wid] = p3;
        }
        __syncthreads();

        float4 q0 = *(const float4*)sP[0];
        float4 q1 = *(const float4*)sP[1];
        float4 q2 = *(const float4*)sP[2];
        float4 q3 = *(const float4*)sP[3];
        float yv[NQB] = { q0.x + q0.y + q0.z + q0.w + binv.x,
                          q1.x + q1.y + q1.z + q1.w + binv.y,
                          q2.x + q2.y + q2.z + q2.w + binv.z,
                          q3.x + q3.y + q3.z + q3.w + binv.w };

        // ---- 2. encoding product state (trig-free, no shuffles) ----
        // lo amp = (A,0), hi amp = B*(cos atan(y^2), sin atan(y^2))
        // A^2=(1-sin atan y)/2, B^2=(1+sin atan y)/2, sin(atan y)=y*rsqrt(1+y^2)
        float2 amp;
        {
            float2 wqv[NQB];
            #pragma unroll
            for (int q = 0; q < NQB; ++q) {
                float y  = yv[q];
                float t2 = y * y;
                float r  = rsqrtf(1.f + t2);
                float s  = y * r;                        // sin(atan y)
                float x2 = fmaf(hs[q], s, 0.5f);         // A^2 or B^2
                float X  = x2 * rsqrtf(x2 + 1e-37f);     // sqrt(x2)
                float r2 = rsqrtf(fmaf(t2, t2, 1.f));    // cos(atan y^2)
                float cr = hq[q] ? r2        : 1.f;
                float si = hq[q] ? t2 * r2   : 0.f;
                wqv[q] = make_float2(X * cr, X * si);
            }
            amp = cmul(cmul(wqv[0], wqv[1]), cmul(wqv[2], wqv[3]));
        }

        // ---- 3. ansatz: gate 0 fused with CNOT ring permutation ----
        float2 a0, a1;
        a0.x = __shfl_sync(FULL, amp.x, src0, 16);
        a0.y = __shfl_sync(FULL, amp.y, src0, 16);
        a1.x = __shfl_sync(FULL, amp.x, src1, 16);
        a1.y = __shfl_sync(FULL, amp.y, src1, 16);

        float2 cur;
        {
            float2 u0 = av0[0], u1 = av1[0];
            cur.x = u0.x*a0.x - u0.y*a0.y + u1.x*a1.x - u1.y*a1.y;
            cur.y = u0.x*a0.y + u0.y*a0.x + u1.x*a1.y + u1.y*a1.x;
        }
        #pragma unroll
        for (int q = 1; q < NQB; ++q) {
            const int  m  = 8 >> q;
            const bool hi = hq[q];
            float ox = __shfl_xor_sync(FULL, cur.x, m, 16);
            float oy = __shfl_xor_sync(FULL, cur.y, m, 16);
            float a0x = hi ? ox : cur.x, a0y = hi ? oy : cur.y;
            float a1x = hi ? cur.x : ox, a1y = hi ? cur.y : oy;
            float2 u0 = av0[q], u1 = av1[q];
            cur.x = u0.x*a0x - u0.y*a0y + u1.x*a1x - u1.y*a1y;
            cur.y = u0.x*a0y + u0.y*a0x + u1.x*a1y + u1.y*a1x;
        }

        // ---- 4. <Z_q> via 4-level Walsh-Hadamard, publish to smem ----
        float w0 = cur.x * cur.x + cur.y * cur.y;
        #pragma unroll
        for (int m = 8; m; m >>= 1) {
            float o = __shfl_xor_sync(FULL, w0, m, 16);
            w0 = (il & m) ? (o - w0) : (w0 + o);
        }
        if (lane < 16 && __popc(il) == 1)
            sZ[wid][4 - __ffs(il)] = w0;     // lane 8->q0, 4->q1, 2->q2, 1->q3
        __syncthreads();

        // ---- 5. projection + LSTM cell (one hidden dim per thread) ----
        float4 z0 = *(const float4*)sZ[0];
        float4 z1 = *(const float4*)sZ[1];
        float4 z2 = *(const float4*)sZ[2];
        float4 z3 = *(const float4*)sZ[3];
        float af = fmaf(z0.x, wo0, fmaf(z0.y, wo1, fmaf(z0.z, wo2, fmaf(z0.w, wo3, bo))));
        float ai = fmaf(z1.x, wo0, fmaf(z1.y, wo1, fmaf(z1.z, wo2, fmaf(z1.w, wo3, bo))));
        float ag = fmaf(z2.x, wo0, fmaf(z2.y, wo1, fmaf(z2.z, wo2, fmaf(z2.w, wo3, bo))));
        float ao = fmaf(z3.x, wo0, fmaf(z3.y, wo1, fmaf(z3.z, wo2, fmaf(z3.w, wo3, bo))));
        float f = fsig(af), i = fsig(ai), g = ftanh(ag), o = fsig(ao);
        c = fmaf(f, c, i * g);
        h = o * ftanh(c);

        out[((size_t)b * SS + t) * HH + tid] = h;
    }

    if (write_tails) {
        size_t base = (size_t)BB * SS * HH;
        out[base + (size_t)b * HH + tid] = h;
        out[base + (size_t)BB * HH + (size_t)b * HH + tid] = c;
    }
}

extern "C" void kernel_launch(void* const* d_in, const int* in_sizes, int n_in,
                              void* d_out, int out_size) {
    const float* x     = (const float*)d_in[0];
    const float* W_in  = (const float*)d_in[1];
    const float* b_in  = (const float*)d_in[2];
    const float* W_out = (const float*)d_in[3];
    const float* b_out = (const float*)d_in[4];
    const float* w_f   = (const float*)d_in[5];
    const float* w_i   = (const float*)d_in[6];
    const float* w_u   = (const float*)d_in[7];
    const float* w_o   = (const float*)d_in[8];
    float* out = (float*)d_out;

    int need_tail = (size_t)out_size >= (size_t)BB * SS * HH + 2 * (size_t)BB * HH;
    qlstm_kernel<<<BB, HH>>>(x, W_in, b_in, W_out, b_out,
                             w_f, w_i, w_u, w_o, out, need_tail);
}

// round 7
// speedup vs baseline: 3.5408x; 1.2349x over previous
#include <cuda_runtime.h>
#include <math.h>

#define NQB 4
#define BB  512
#define SS  256
#define DD  64
#define HH  128
#define FULL 0xffffffffu

__device__ __forceinline__ float2 cmul(float2 a, float2 b) {
    return make_float2(fmaf(a.x, b.x, -a.y * b.y), fmaf(a.x, b.y, a.y * b.x));
}
__device__ __forceinline__ float tanha(float x) {
    float r;
    asm("tanh.approx.f32 %0, %1;" : "=f"(r) : "f"(x));
    return r;
}

// source index after the CNOT ring (0,1)(1,2)(2,3)(3,0), gather form
__device__ __forceinline__ int cnot_src(int i) {
    i ^= (i & 1) ? 8 : 0;   // CNOT(3,0)
    i ^= (i & 2) ? 1 : 0;   // CNOT(2,3)
    i ^= (i & 4) ? 2 : 0;   // CNOT(1,2)
    i ^= (i & 8) ? 4 : 0;   // CNOT(0,1)
    return i;
}

__global__ __launch_bounds__(128)
void qlstm_kernel(const float* __restrict__ x,
                  const float* __restrict__ W_in,
                  const float* __restrict__ b_in,
                  const float* __restrict__ W_out,
                  const float* __restrict__ b_out,
                  const float* __restrict__ w_f,
                  const float* __restrict__ w_i,
                  const float* __restrict__ w_u,
                  const float* __restrict__ w_o,
                  float* __restrict__ out,
                  int write_tails)
{
    __shared__ __align__(16) float sP[4][4];   // [j][warp] partial y sums
    __shared__ __align__(16) float sZ[4][4];   // [gate][qubit] <Z>

    const int tid  = threadIdx.x;
    const int lane = tid & 31;
    const int wid  = tid >> 5;          // warp = gate: 0=f 1=i 2=u 3=o
    const int il   = lane & 15;         // amplitude index (lanes 16-31 mirror)
    const int b    = blockIdx.x;

    // ---- per-thread constants (registers) ----
    float4 wi = *(const float4*)(W_in + 4 * tid);                 // W_in row for h-dim tid
    float4 wx = make_float4(0.f, 0.f, 0.f, 0.f);
    if (tid < DD) wx = *(const float4*)(W_in + 4 * (HH + tid));   // W_in row for x-dim tid
    float4 binv = *(const float4*)(b_in);
    // halved projection weights: accumulators become (W_out z + b_out)/2,
    // so sigmoid(a) = 0.5 + 0.5*tanh(a_half) and tanh(a) = tanh(2*a_half).
    float wo0 = 0.5f * W_out[tid];
    float wo1 = 0.5f * W_out[HH + tid];
    float wo2 = 0.5f * W_out[2 * HH + tid];
    float wo3 = 0.5f * W_out[3 * HH + tid];
    float bo  = 0.5f * b_out[tid];

    bool  hq[NQB];
    float hs[NQB];
    #pragma unroll
    for (int q = 0; q < NQB; ++q) {
        hq[q] = (il >> (3 - q)) & 1;
        hs[q] = hq[q] ? 0.5f : -0.5f;
    }

    // fused ansatz U = RZ*RY*RX for THIS warp's gate; keep the row this lane needs
    float2 av0[NQB], av1[NQB];
    {
        const float* wg = (wid == 0) ? w_f : (wid == 1) ? w_i : (wid == 2) ? w_u : w_o;
        #pragma unroll
        for (int q = 0; q < NQB; ++q) {
            float sa, ca, sb, cb, sg, cg;
            sincosf(wg[q]           * 0.5f, &sa, &ca);
            sincosf(wg[NQB + q]     * 0.5f, &sb, &cb);
            sincosf(wg[2 * NQB + q] * 0.5f, &sg, &cg);
            float2 m00 = make_float2( cb * ca,  sb * sa);
            float2 m01 = make_float2(-sb * ca, -cb * sa);
            float2 m10 = make_float2( sb * ca, -cb * sa);
            float2 m11 = make_float2( cb * ca, -sb * sa);
            float2 e0  = make_float2(cg, -sg);
            float2 e1  = make_float2(cg,  sg);
            if (hq[q]) { av0[q] = cmul(e1, m10); av1[q] = cmul(e1, m11); }
            else       { av0[q] = cmul(e0, m00); av1[q] = cmul(e0, m01); }
        }
    }

    const int src0 = cnot_src(il & 7);   // bit8=0 partner, CNOT-ring fused
    const int src1 = cnot_src(il | 8);   // bit8=1 partner

    const float* xb = x + (size_t)b * SS * DD;
    float xv = (tid < DD) ? xb[tid] : 0.f;

    float h = 0.f, c = 0.f;

    for (int t = 0; t < SS; ++t) {
        // ---- 1. y = [h, x_t] @ W_in + b_in (warp reduce + smem combine) ----
        float p0 = fmaf(h, wi.x, xv * wx.x);
        float p1 = fmaf(h, wi.y, xv * wx.y);
        float p2 = fmaf(h, wi.z, xv * wx.z);
        float p3 = fmaf(h, wi.w, xv * wx.w);
        if (tid < DD && t + 1 < SS) xv = xb[(t + 1) * DD + tid];   // prefetch

        #pragma unroll
        for (int off = 16; off; off >>= 1) {
            p0 += __shfl_xor_sync(FULL, p0, off);
            p1 += __shfl_xor_sync(FULL, p1, off);
            p2 += __shfl_xor_sync(FULL, p2, off);
            p3 += __shfl_xor_sync(FULL, p3, off);
        }
        if (lane == 0) {
            sP[0][wid] = p0; sP[1][wid] = p1; sP[2][wid] = p2; sP[3][wid] = p3;
        }
        __syncthreads();

        float4 q0 = *(const float4*)sP[0];
        float4 q1 = *(const float4*)sP[1];
        float4 q2 = *(const float4*)sP[2];
        float4 q3 = *(const float4*)sP[3];
        float yv[NQB] = { q0.x + q0.y + q0.z + q0.w + binv.x,
                          q1.x + q1.y + q1.z + q1.w + binv.y,
                          q2.x + q2.y + q2.z + q2.w + binv.z,
                          q3.x + q3.y + q3.z + q3.w + binv.w };

        // ---- 2. encoding product state, combined-normalization form ----
        // per-qubit factor: lo -> (sqrt(x2),0) ; hi -> sqrt(x2)*(1,t2)/sqrt(1+t4)
        // with x2 = 0.5 + hs*sin(atan y), sin(atan y) = y*rsqrt(1+y^2).
        // amp = z * sqrt(P/D), z = prod(1, t2[hi]), P = prod x2, D = prod(1+t4[hi])
        float2 amp;
        {
            float P = 1.f, Dm = 1.f;
            float zx = 1.f, zy = 0.f;
            #pragma unroll
            for (int q = 0; q < NQB; ++q) {
                float y  = yv[q];
                float t2 = y * y;
                float r  = rsqrtf(1.f + t2);             // MUFU
                float s  = y * r;                        // sin(atan y)
                float x2 = fmaf(hs[q], s, 0.5f);
                P *= x2;
                float tq = hq[q] ? t2 : 0.f;
                float nzx = fmaf(-zy, tq, zx);
                float nzy = fmaf( zx, tq, zy);
                zx = nzx; zy = nzy;
                Dm *= fmaf(tq, tq, 1.f);
            }
            float m = P * rsqrtf(P * Dm);                // sqrt(P/D), 1 MUFU
            amp = make_float2(zx * m, zy * m);
        }

        // ---- 3. ansatz: gate 0 fused with CNOT ring permutation ----
        float2 a0, a1;
        a0.x = __shfl_sync(FULL, amp.x, src0, 16);
        a0.y = __shfl_sync(FULL, amp.y, src0, 16);
        a1.x = __shfl_sync(FULL, amp.x, src1, 16);
        a1.y = __shfl_sync(FULL, amp.y, src1, 16);

        float2 cur;
        {
            float2 u0 = av0[0], u1 = av1[0];
            cur.x = u0.x*a0.x - u0.y*a0.y + u1.x*a1.x - u1.y*a1.y;
            cur.y = u0.x*a0.y + u0.y*a0.x + u1.x*a1.y + u1.y*a1.x;
        }
        #pragma unroll
        for (int q = 1; q < NQB; ++q) {
            const int  m  = 8 >> q;
            const bool hi = hq[q];
            float ox = __shfl_xor_sync(FULL, cur.x, m, 16);
            float oy = __shfl_xor_sync(FULL, cur.y, m, 16);
            float a0x = hi ? ox : cur.x, a0y = hi ? oy : cur.y;
            float a1x = hi ? cur.x : ox, a1y = hi ? cur.y : oy;
            float2 u0 = av0[q], u1 = av1[q];
            cur.x = u0.x*a0x - u0.y*a0y + u1.x*a1x - u1.y*a1y;
            cur.y = u0.x*a0y + u0.y*a0x + u1.x*a1y + u1.y*a1x;
        }

        // ---- 4. <Z_q> via 4-level Walsh-Hadamard, publish to smem ----
        float w0 = cur.x * cur.x + cur.y * cur.y;
        #pragma unroll
        for (int m = 8; m; m >>= 1) {
            float o = __shfl_xor_sync(FULL, w0, m, 16);
            w0 = (il & m) ? (o - w0) : (w0 + o);
        }
        if (lane < 16 && __popc(il) == 1)
            sZ[wid][4 - __ffs(il)] = w0;     // lane 8->q0, 4->q1, 2->q2, 1->q3
        __syncthreads();

        // ---- 5. projection + LSTM cell (one hidden dim per thread) ----
        // accumulators are pre-halved; sigmoid(a)=0.5+0.5*tanh(a/2), tanh(a)=tanh(2*(a/2))
        float4 z0 = *(const float4*)sZ[0];
        float4 z1 = *(const float4*)sZ[1];
        float4 z2 = *(const float4*)sZ[2];
        float4 z3 = *(const float4*)sZ[3];
        float af = fmaf(z0.x, wo0, fmaf(z0.y, wo1, fmaf(z0.z, wo2, fmaf(z0.w, wo3, bo))));
        float ai = fmaf(z1.x, wo0, fmaf(z1.y, wo1, fmaf(z1.z, wo2, fmaf(z1.w, wo3, bo))));
        float ag = fmaf(z2.x, wo0, fmaf(z2.y, wo1, fmaf(z2.z, wo2, fmaf(z2.w, wo3, bo))));
        float ao = fmaf(z3.x, wo0, fmaf(z3.y, wo1, fmaf(z3.z, wo2, fmaf(z3.w, wo3, bo))));
        float f = fmaf(0.5f, tanha(af), 0.5f);
        float i = fmaf(0.5f, tanha(ai), 0.5f);
        float g = tanha(ag + ag);
        float o = fmaf(0.5f, tanha(ao), 0.5f);
        c = fmaf(f, c, i * g);
        h = o * tanha(c);

        out[((size_t)b * SS + t) * HH + tid] = h;
    }

    if (write_tails) {
        size_t base = (size_t)BB * SS * HH;
        out[base + (size_t)b * HH + tid] = h;
        out[base + (size_t)BB * HH + (size_t)b * HH + tid] = c;
    }
}

extern "C" void kernel_launch(void* const* d_in, const int* in_sizes, int n_in,
                              void* d_out, int out_size) {
    const float* x     = (const float*)d_in[0];
    const float* W_in  = (const float*)d_in[1];
    const float* b_in  = (const float*)d_in[2];
    const float* W_out = (const float*)d_in[3];
    const float* b_out = (const float*)d_in[4];
    const float* w_f   = (const float*)d_in[5];
    const float* w_i   = (const float*)d_in[6];
    const float* w_u   = (const float*)d_in[7];
    const float* w_o   = (const float*)d_in[8];
    float* out = (float*)d_out;

    int need_tail = (size_t)out_size >= (size_t)BB * SS * HH + 2 * (size_t)BB * HH;
    qlstm_kernel<<<BB, HH>>>(x, W_in, b_in, W_out, b_out,
                             w_f, w_i, w_u, w_o, out, need_tail);
}

// round 9
// speedup vs baseline: 3.6669x; 1.0356x over previous
#include <cuda_runtime.h>
#include <math.h>

#define NQB 4
#define BB  512
#define SS  256
#define DD  64
#define HH  128
#define FULL 0xffffffffu

__device__ __forceinline__ float2 cmul(float2 a, float2 b) {
    return make_float2(fmaf(a.x, b.x, -a.y * b.y), fmaf(a.x, b.y, a.y * b.x));
}
__device__ __forceinline__ float tanha(float x) {
    float r;
    asm("tanh.approx.f32 %0, %1;" : "=f"(r) : "f"(x));
    return r;
}

// source index after the CNOT ring (0,1)(1,2)(2,3)(3,0), gather form
__device__ __forceinline__ int cnot_src(int i) {
    i ^= (i & 1) ? 8 : 0;   // CNOT(3,0)
    i ^= (i & 2) ? 1 : 0;   // CNOT(2,3)
    i ^= (i & 4) ? 2 : 0;   // CNOT(1,2)
    i ^= (i & 8) ? 4 : 0;   // CNOT(0,1)
    return i;
}

__global__ __launch_bounds__(128)
void qlstm_kernel(const float* __restrict__ x,
                  const float* __restrict__ W_in,
                  const float* __restrict__ b_in,
                  const float* __restrict__ W_out,
                  const float* __restrict__ b_out,
                  const float* __restrict__ w_f,
                  const float* __restrict__ w_i,
                  const float* __restrict__ w_u,
                  const float* __restrict__ w_o,
                  float* __restrict__ out,
                  int write_tails)
{
    __shared__ __align__(16) float sP[4][4];   // [j][warp] partial y sums
    __shared__ __align__(16) float sZ[4][4];   // [gate][qubit] <Z>

    const int tid  = threadIdx.x;
    const int lane = tid & 31;
    const int wid  = tid >> 5;          // warp = gate: 0=f 1=i 2=u 3=o
    const int il   = lane & 15;         // amplitude index (lanes 16-31 mirror)
    const int b    = blockIdx.x;

    // ---- per-thread constants (registers) ----
    float4 wi = *(const float4*)(W_in + 4 * tid);                 // W_in row for h-dim tid
    float4 wx = make_float4(0.f, 0.f, 0.f, 0.f);
    if (tid < DD) wx = *(const float4*)(W_in + 4 * (HH + tid));   // W_in row for x-dim tid
    float4 binv = *(const float4*)(b_in);
    // halved projection weights: accumulators become (W_out z + b_out)/2,
    // so sigmoid(a) = 0.5 + 0.5*tanh(a_half) and tanh(a) = tanh(2*a_half).
    float wo0 = 0.5f * W_out[tid];
    float wo1 = 0.5f * W_out[HH + tid];
    float wo2 = 0.5f * W_out[2 * HH + tid];
    float wo3 = 0.5f * W_out[3 * HH + tid];
    float bo  = 0.5f * b_out[tid];

    bool  hq[NQB];
    float hs[NQB];
    #pragma unroll
    for (int q = 0; q < NQB; ++q) {
        hq[q] = (il >> (3 - q)) & 1;
        hs[q] = hq[q] ? 0.5f : -0.5f;
    }

    // fused ansatz U = RZ*RY*RX for THIS warp's gate; keep the row this lane needs
    float2 av0[NQB], av1[NQB];
    {
        const float* wg = (wid == 0) ? w_f : (wid == 1) ? w_i : (wid == 2) ? w_u : w_o;
        #pragma unroll
        for (int q = 0; q < NQB; ++q) {
            float sa, ca, sb, cb, sg, cg;
            sincosf(wg[q]           * 0.5f, &sa, &ca);
            sincosf(wg[NQB + q]     * 0.5f, &sb, &cb);
            sincosf(wg[2 * NQB + q] * 0.5f, &sg, &cg);
            float2 m00 = make_float2( cb * ca,  sb * sa);
            float2 m01 = make_float2(-sb * ca, -cb * sa);
            float2 m10 = make_float2( sb * ca, -cb * sa);
            float2 m11 = make_float2( cb * ca, -sb * sa);
            float2 e0  = make_float2(cg, -sg);
            float2 e1  = make_float2(cg,  sg);
            if (hq[q]) { av0[q] = cmul(e1, m10); av1[q] = cmul(e1, m11); }
            else       { av0[q] = cmul(e0, m00); av1[q] = cmul(e0, m01); }
        }
    }

    const int src0 = cnot_src(il & 7);   // bit8=0 partner, CNOT-ring fused
    const int src1 = cnot_src(il | 8);   // bit8=1 partner

    // reduce-scatter layout helpers (hoisted predicates)
    const bool rb16 = (lane & 16) != 0;
    const bool rb8  = (lane & 8)  != 0;
    const bool isWriterP = ((lane & 7) == 0);    // lanes 0,8,16,24
    const int  pj        = lane >> 3;            // j index this lane's group reduces
    const bool isWriterZ = (lane < 16) && (__popc(il) == 1);
    const int  zj        = 4 - __ffs(il);        // lane 8->q0, 4->q1, 2->q2, 1->q3

    const float* xb = x + (size_t)b * SS * DD;
    float xv = (tid < DD) ? xb[tid] : 0.f;

    float h = 0.f, c = 0.f;
    float* op = out + (size_t)b * SS * HH + tid;

    for (int t = 0; t < SS; ++t) {
        // ---- 1. y = [h, x_t] @ W_in + b_in ----
        float p0 = fmaf(h, wi.x, xv * wx.x);
        float p1 = fmaf(h, wi.y, xv * wx.y);
        float p2 = fmaf(h, wi.z, xv * wx.z);
        float p3 = fmaf(h, wi.w, xv * wx.w);
        if (tid < DD && t + 1 < SS) xv = xb[(t + 1) * DD + tid];   // prefetch

        // multi-value reduce-scatter butterfly: 6 shuffles for all 4 sums.
        // lane group (bit16,bit8) ends holding y_{2*b16+b8} summed over 32 lanes.
        float t0 = rb16 ? p0 : p2;
        t0 = __shfl_xor_sync(FULL, t0, 16);
        float ra = (rb16 ? p2 : p0) + t0;
        float t1 = rb16 ? p1 : p3;
        t1 = __shfl_xor_sync(FULL, t1, 16);
        float rbv = (rb16 ? p3 : p1) + t1;
        float t2s = rb8 ? ra : rbv;
        t2s = __shfl_xor_sync(FULL, t2s, 8);
        float k = (rb8 ? rbv : ra) + t2s;
        k += __shfl_xor_sync(FULL, k, 4);
        k += __shfl_xor_sync(FULL, k, 2);
        k += __shfl_xor_sync(FULL, k, 1);
        if (isWriterP) sP[pj][wid] = k;
        __syncthreads();

        float4 q0 = *(const float4*)sP[0];
        float4 q1 = *(const float4*)sP[1];
        float4 q2 = *(const float4*)sP[2];
        float4 q3 = *(const float4*)sP[3];
        float yv[NQB] = { q0.x + q0.y + q0.z + q0.w + binv.x,
                          q1.x + q1.y + q1.z + q1.w + binv.y,
                          q2.x + q2.y + q2.z + q2.w + binv.z,
                          q3.x + q3.y + q3.z + q3.w + binv.w };

        // ---- 2. encoding product state, combined-normalization form ----
        // amp = z * sqrt(P/D), z = prod(1, t2[hi]), P = prod x2, D = prod(1+t4[hi])
        float2 amp;
        {
            float P = 1.f, Dm = 1.f;
            float zx = 1.f, zy = 0.f;
            #pragma unroll
            for (int q = 0; q < NQB; ++q) {
                float y  = yv[q];
                float t2 = y * y;
                float r  = rsqrtf(1.f + t2);             // MUFU
                float s  = y * r;                        // sin(atan y)
                float x2 = fmaf(hs[q], s, 0.5f);
                P *= x2;
                float tq = hq[q] ? t2 : 0.f;
                float nzx = fmaf(-zy, tq, zx);
                float nzy = fmaf( zx, tq, zy);
                zx = nzx; zy = nzy;
                Dm *= fmaf(tq, tq, 1.f);
            }
            float m = P * rsqrtf(P * Dm);                // sqrt(P/D), 1 MUFU
            amp = make_float2(zx * m, zy * m);
        }

        // ---- 3. ansatz: gate 0 fused with CNOT ring permutation ----
        float2 a0, a1;
        a0.x = __shfl_sync(FULL, amp.x, src0, 16);
        a0.y = __shfl_sync(FULL, amp.y, src0, 16);
        a1.x = __shfl_sync(FULL, amp.x, src1, 16);
        a1.y = __shfl_sync(FULL, amp.y, src1, 16);

        float2 cur;
        {
            float2 u0 = av0[0], u1 = av1[0];
            cur.x = u0.x*a0.x - u0.y*a0.y + u1.x*a1.x - u1.y*a1.y;
            cur.y = u0.x*a0.y + u0.y*a0.x + u1.x*a1.y + u1.y*a1.x;
        }
        #pragma unroll
        for (int q = 1; q < NQB; ++q) {
            const int  m  = 8 >> q;
            const bool hi = hq[q];
            float ox = __shfl_xor_sync(FULL, cur.x, m, 16);
            float oy = __shfl_xor_sync(FULL, cur.y, m, 16);
            float a0x = hi ? ox : cur.x, a0y = hi ? oy : cur.y;
            float a1x = hi ? cur.x : ox, a1y = hi ? cur.y : oy;
            float2 u0 = av0[q], u1 = av1[q];
            cur.x = u0.x*a0x - u0.y*a0y + u1.x*a1x - u1.y*a1y;
            cur.y = u0.x*a0y + u0.y*a0x + u1.x*a1y + u1.y*a1x;
        }

        // ---- 4. <Z_q> via 4-level Walsh-Hadamard, publish to smem ----
        float w0 = cur.x * cur.x + cur.y * cur.y;
        #pragma unroll
        for (int m = 8; m; m >>= 1) {
            float o = __shfl_xor_sync(FULL, w0, m, 16);
            w0 = (il & m) ? (o - w0) : (w0 + o);
        }
        if (isWriterZ) sZ[wid][zj] = w0;
        __syncthreads();

        // ---- 5. projection + LSTM cell (one hidden dim per thread) ----
        float4 z0 = *(const float4*)sZ[0];
        float4 z1 = *(const float4*)sZ[1];
        float4 z2 = *(const float4*)sZ[2];
        float4 z3 = *(const float4*)sZ[3];
        float af = fmaf(z0.x, wo0, fmaf(z0.y, wo1, fmaf(z0.z, wo2, fmaf(z0.w, wo3, bo))));
        float ai = fmaf(z1.x, wo0, fmaf(z1.y, wo1, fmaf(z1.z, wo2, fmaf(z1.w, wo3, bo))));
        float ag = fmaf(z2.x, wo0, fmaf(z2.y, wo1, fmaf(z2.z, wo2, fmaf(z2.w, wo3, bo))));
        float ao = fmaf(z3.x, wo0, fmaf(z3.y, wo1, fmaf(z3.z, wo2, fmaf(z3.w, wo3, bo))));
        float f = fmaf(0.5f, tanha(af), 0.5f);
        float i = fmaf(0.5f, tanha(ai), 0.5f);
        float g = tanha(ag + ag);
        float o = fmaf(0.5f, tanha(ao), 0.5f);
        c = fmaf(f, c, i * g);
        h = o * tanha(c);

        *op = h;
        op += HH;
    }

    if (write_tails) {
        size_t base = (size_t)BB * SS * HH;
        out[base + (size_t)b * HH + tid] = h;
        out[base + (size_t)BB * HH + (size_t)b * HH + tid] = c;
    }
}

extern "C" void kernel_launch(void* const* d_in, const int* in_sizes, int n_in,
                              void* d_out, int out_size) {
    const float* x     = (const float*)d_in[0];
    const float* W_in  = (const float*)d_in[1];
    const float* b_in  = (const float*)d_in[2];
    const float* W_out = (const float*)d_in[3];
    const float* b_out = (const float*)d_in[4];
    const float* w_f   = (const float*)d_in[5];
    const float* w_i   = (const float*)d_in[6];
    const float* w_u   = (const float*)d_in[7];
    const float* w_o   = (const float*)d_in[8];
    float* out = (float*)d_out;

    int need_tail = (size_t)out_size >= (size_t)BB * SS * HH + 2 * (size_t)BB * HH;
    qlstm_kernel<<<BB, HH>>>(x, W_in, b_in, W_out, b_out,
                             w_f, w_i, w_u, w_o, out, need_tail);
}